// round 10
// baseline (speedup 1.0000x reference)
#include <cuda_runtime.h>
#include <cuda_bf16.h>
#include <cstdint>

// Problem constants
#define BB   256
#define TT   2048
#define IND  6
#define HID  64
#define GG   192          // 3*HID
#define DPK  64
#define NROWS (BB*TT)     // 524288
#define EPS  1e-5f
#define CH   4            // chains per GRU CTA (4 => 2 warps/SMSP, cross-chain)

typedef unsigned long long u64;

// ---------------- scratch (allocation-free: __device__ globals) -------------
__device__ float g_x[(size_t)NROWS * HID];       // 128 MB : post input-proj activations
// gi J-MAJOR: index = row*GG + gate*64 + j  (warp-coalesced loads in k_gru)
// biases pre-folded: r,z gates carry b_ih+b_hh; n gate carries b_ih only.
__device__ float g_gi[(size_t)NROWS * GG];       // 402 MB
__device__ float g_hseq[(size_t)NROWS * HID];    // 128 MB : GRU hidden states [b][t][j]

// ---------------- packed f32x2 helpers --------------------------------------
__device__ __forceinline__ u64 fma2(u64 a, u64 b, u64 c) {
    u64 d;
    asm("fma.rn.f32x2 %0, %1, %2, %3;" : "=l"(d) : "l"(a), "l"(b), "l"(c));
    return d;
}
__device__ __forceinline__ u64 pack2(float a, float b) {
    u64 r;
    asm("mov.b64 %0, {%1,%2};" : "=l"(r) : "f"(a), "f"(b));
    return r;
}
__device__ __forceinline__ float psum(u64 a) {
    return __uint_as_float((unsigned)(a & 0xffffffffull)) +
           __uint_as_float((unsigned)(a >> 32));
}

// EXACT-path activations (validated rel_err ~2.5e-7 over the full recurrence).
// tanh.approx is banned inside the recurrence (R5: errors compound to ~0.15).
__device__ __forceinline__ float sigmoidf_(float x) {
    return __fdividef(1.f, 1.f + __expf(-x));
}
__device__ __forceinline__ float tanhf_(float x) {
    float e = __expf(2.f * x);
    return 1.f - __fdividef(2.f, e + 1.f);   // safe at e->inf (->1) and e->0 (->-1)
}

// ================== K1a: input proj + LN + exact GELU ======================
// one warp per (b,t) row; each lane owns output cols lane, lane+32
__global__ void k_inproj(const float* __restrict__ ce,
                         const float* __restrict__ w1,
                         const float* __restrict__ b1,
                         const float* __restrict__ g1,
                         const float* __restrict__ bb1)
{
    const int wid  = threadIdx.x >> 5;
    const int lane = threadIdx.x & 31;
    const size_t row = (size_t)blockIdx.x * 8 + wid;   // grid = NROWS/8

    const float* c = ce + row * IND;
    float v0 = b1[lane], v1 = b1[lane + 32];
#pragma unroll
    for (int i = 0; i < IND; ++i) {
        float ci = __ldg(c + i);
        v0 = fmaf(ci, w1[i * HID + lane],      v0);
        v1 = fmaf(ci, w1[i * HID + lane + 32], v1);
    }
    float s = v0 + v1;
#pragma unroll
    for (int o = 16; o; o >>= 1) s += __shfl_xor_sync(0xffffffffu, s, o);
    const float m = s * (1.f / 64.f);
    const float d0 = v0 - m, d1 = v1 - m;
    float q = d0 * d0 + d1 * d1;
#pragma unroll
    for (int o = 16; o; o >>= 1) q += __shfl_xor_sync(0xffffffffu, q, o);
    const float rs = rsqrtf(q * (1.f / 64.f) + EPS);
    const float y0 = d0 * rs * g1[lane]      + bb1[lane];
    const float y1 = d1 * rs * g1[lane + 32] + bb1[lane + 32];
    const float k = 0.70710678118654752f;
    g_x[row * HID + lane]      = 0.5f * y0 * (1.f + erff(y0 * k));
    g_x[row * HID + lane + 32] = 0.5f * y1 * (1.f + erff(y1 * k));
}

// ================== K1b: gi = x @ W_ih^T + bias  (j-major output) ==========
// gate-stationary: thread g keeps W_ih[g,:] in 32 packed-u64 registers,
// 8 rows of x staged in smem per iteration; direct coalesced output write.
// Bias folding: gates r,z get b_ih+b_hh; gate n gets b_ih only.
__global__ void __launch_bounds__(192) k_gi(const float* __restrict__ Wih,
                                            const float* __restrict__ bih,
                                            const float* __restrict__ bhh)
{
    const int g = threadIdx.x;
    u64 w[32];
    const u64* wrow = (const u64*)(Wih + g * HID);
#pragma unroll
    for (int k = 0; k < 32; ++k) w[k] = wrow[k];
    const int gate = g >> 6;
    const float bi = bih[g] + (gate < 2 ? bhh[g] : 0.f);

    __shared__ __align__(16) float x_sh[8 * HID];

    for (size_t r0 = (size_t)blockIdx.x * 8; r0 < (size_t)NROWS;
         r0 += (size_t)gridDim.x * 8) {
        if (g < 128)
            ((float4*)x_sh)[g] = ((const float4*)(g_x + r0 * HID))[g];
        __syncthreads();
#pragma unroll
        for (int rr = 0; rr < 8; ++rr) {
            u64 a0 = 0, a1 = 0;
            const ulonglong2* xv = (const ulonglong2*)(x_sh + rr * HID);
#pragma unroll
            for (int kk = 0; kk < 16; ++kk) {
                ulonglong2 p = xv[kk];
                a0 = fma2(w[2 * kk],     p.x, a0);
                a1 = fma2(w[2 * kk + 1], p.y, a1);
            }
            g_gi[(r0 + rr) * GG + g] = psum(a0) + psum(a1) + bi;
        }
        __syncthreads();
    }
}

// ================== K2: sequential GRU recurrence ===========================
// grid = 64 CTAs, block = 256 threads = 4 chains x 64 threads (2 warps each).
// IDENTICAL inner loop to the R8 best (no K-split, full 64-wide dots, all
// three gate rows register-resident: 96 u64). The ONLY change vs R8: 4
// chains per CTA instead of 2, so each SMSP hosts TWO warps from two
// DIFFERENT chains (chain c -> warps 2c,2c+1; SMSP s gets chains s>>1 ... ):
//   chain0: SMSP 0,1   chain1: SMSP 2,3   chain2: SMSP 0,1   chain3: SMSP 2,3
// Their 64-thread named barriers drift independently, so when one chain sits
// in its exposed serial-latency window (LDS -> dot chain -> MUFU -> bar), the
// co-resident chain issues its fma2 stream -> latency hidden at unchanged
// per-chain issue cost (the R9 K-split bought the same overlap but paid shfl
// + duplicated-misc overhead for it; this is overlap for free).
// h in 16-slot smem ring; coalesced float4 flush every 8 steps.
// gi j-major, in-place reload depth 4. One named barrier (64 thr) per step.
__global__ void __launch_bounds__(256, 1) k_gru(const float* __restrict__ Whh,
                                                const float* __restrict__ bhh)
{
    const int tid   = threadIdx.x;
    const int chain = tid >> 6;          // 0..3
    const int j     = tid & 63;
    const size_t brow = (size_t)blockIdx.x * CH + chain;
    const unsigned barid = 1 + chain;

    __shared__ __align__(16) float ring[16][CH][64];  // 16 KB h history

    // all three gate rows register-resident: 96 u64
    u64 wr[32], wz[32], wn[32];
    {
        const u64* rrow = (const u64*)(Whh + (size_t)j * HID);
        const u64* zrow = (const u64*)(Whh + (size_t)(64 + j) * HID);
        const u64* nrow = (const u64*)(Whh + (size_t)(128 + j) * HID);
#pragma unroll
        for (int k = 0; k < 32; ++k) { wr[k] = rrow[k]; wz[k] = zrow[k]; wn[k] = nrow[k]; }
    }
    const float bhn = bhh[128 + j];   // only n-gate hidden bias kept (inside r*(..))

    ring[15][chain][j] = 0.f;        // h_{-1} = 0
    float hprev = 0.f;

    const float* gib = g_gi + brow * (size_t)TT * GG + j;   // + t*GG + gate*64
    float* hbase = g_hseq + brow * (size_t)TT * HID;

    // gi block buffer: current 4 steps (12 scalars), each reloaded in place
    // right after consumption with the value 4 steps ahead (coalesced LDG.32).
    float cr0 = __ldg(gib + 0 * GG), cz0 = __ldg(gib + 0 * GG + 64), cn0 = __ldg(gib + 0 * GG + 128);
    float cr1 = __ldg(gib + 1 * GG), cz1 = __ldg(gib + 1 * GG + 64), cn1 = __ldg(gib + 1 * GG + 128);
    float cr2 = __ldg(gib + 2 * GG), cz2 = __ldg(gib + 2 * GG + 64), cn2 = __ldg(gib + 2 * GG + 128);
    float cr3 = __ldg(gib + 3 * GG), cz3 = __ldg(gib + 3 * GG + 64), cn3 = __ldg(gib + 3 * GG + 128);

    asm volatile("bar.sync %0, 64;" :: "r"(barid) : "memory");

    auto step = [&](const int t, const float ir, const float iz, const float inn) {
        const ulonglong2* hv = (const ulonglong2*)ring[(t + 15) & 15][chain];
        u64 ar = 0, az = 0, an = 0;            // single accum chain per gate
#pragma unroll
        for (int kk = 0; kk < 16; ++kk) {      // full 64-wide dot: 16 x LDS.128
            const ulonglong2 p = hv[kk];
            ar = fma2(wr[2 * kk],     p.x, ar);
            az = fma2(wz[2 * kk],     p.x, az);
            an = fma2(wn[2 * kk],     p.x, an);
            ar = fma2(wr[2 * kk + 1], p.y, ar);
            az = fma2(wz[2 * kk + 1], p.y, az);
            an = fma2(wn[2 * kk + 1], p.y, an);
        }
        const float pr = psum(ar);
        const float pz = psum(az);
        const float pn = psum(an);

        const float r = sigmoidf_(ir + pr);             // biases pre-folded in gi
        const float z = sigmoidf_(iz + pz);
        const float n = tanhf_(inn + r * (pn + bhn));
        const float hnew = fmaf(z, hprev - n, n);       // (1-z)*n + z*h

        ring[t & 15][chain][j] = hnew;
        hprev = hnew;
        asm volatile("bar.sync %0, 64;" :: "r"(barid) : "memory");
    };

#pragma unroll 1
    for (int blk = 0; blk < TT / 4; ++blk) {
        const int t0 = blk * 4;
        const bool pf = (blk + 1 < TT / 4);
        const float* p = gib + (size_t)(t0 + 4) * GG;

        { const float ir = cr0, iz = cz0, inn = cn0;
          if (pf) { cr0 = __ldg(p + 0 * GG); cz0 = __ldg(p + 0 * GG + 64); cn0 = __ldg(p + 0 * GG + 128); }
          step(t0 + 0, ir, iz, inn); }
        { const float ir = cr1, iz = cz1, inn = cn1;
          if (pf) { cr1 = __ldg(p + 1 * GG); cz1 = __ldg(p + 1 * GG + 64); cn1 = __ldg(p + 1 * GG + 128); }
          step(t0 + 1, ir, iz, inn); }
        { const float ir = cr2, iz = cz2, inn = cn2;
          if (pf) { cr2 = __ldg(p + 2 * GG); cz2 = __ldg(p + 2 * GG + 64); cn2 = __ldg(p + 2 * GG + 128); }
          step(t0 + 2, ir, iz, inn); }
        { const float ir = cr3, iz = cz3, inn = cn3;
          if (pf) { cr3 = __ldg(p + 3 * GG); cz3 = __ldg(p + 3 * GG + 64); cn3 = __ldg(p + 3 * GG + 128); }
          step(t0 + 3, ir, iz, inn); }

        if (blk & 1) {
            // flush steps tb..tb+7 (ring slots (tb&15)..+7), coalesced.
            // Safe: these slots are next overwritten >= 9 barriers later.
            const int tb = t0 - 4;               // multiple of 8
            const int sb = tb & 15;              // 0 or 8
#pragma unroll
            for (int q = 0; q < 2; ++q) {
                const int idx  = q * 64 + j;     // 0..127
                const int toff = idx >> 4;       // 0..7
                const int jq   = idx & 15;       // float4 index within row
                const float4 v = ((const float4*)ring[sb + toff][chain])[jq];
                ((float4*)(hbase + (size_t)(tb + toff) * HID))[jq] = v;
            }
        }
    }
}

// ================== K3: out proj + LN =======================================
// 256 threads / 8 warps; w2 packed in smem [k2][64] (conflict-free LDS.64);
// each warp processes 4 rows per iteration (MLP_p1=4), lane owns cols lane,lane+32.
__global__ void __launch_bounds__(256) k_outproj(const float* __restrict__ w2,
                                                 const float* __restrict__ b2,
                                                 const float* __restrict__ g2,
                                                 const float* __restrict__ bb2,
                                                 float* __restrict__ out)
{
    const int tid  = threadIdx.x;
    const int wid  = tid >> 5;
    const int lane = tid & 31;
    const int j0 = lane, j1 = lane + 32;

    __shared__ __align__(16) u64   w2p[32][64];     // 16 KB
    __shared__ __align__(16) float hst[8][4][64];   // 8 KB, per-warp staging

    for (int idx = tid; idx < 32 * 64; idx += 256) {
        const int k2 = idx >> 6, jj = idx & 63;
        w2p[k2][jj] = pack2(w2[(size_t)(2 * k2) * DPK + jj],
                            w2[(size_t)(2 * k2 + 1) * DPK + jj]);
    }
    __syncthreads();

    const float bo0 = b2[j0], bo1 = b2[j1];
    const float lg0 = g2[j0], lg1 = g2[j1];
    const float lb0 = bb2[j0], lb1 = bb2[j1];

    const size_t stride = (size_t)gridDim.x * 32;
    for (size_t base = (size_t)blockIdx.x * 32 + wid * 4; base < (size_t)NROWS;
         base += stride) {
        // 4 rows in flight (front-batched LDG.64s)
        const float2 h0 = ((const float2*)(g_hseq + (base + 0) * HID))[lane];
        const float2 h1 = ((const float2*)(g_hseq + (base + 1) * HID))[lane];
        const float2 h2 = ((const float2*)(g_hseq + (base + 2) * HID))[lane];
        const float2 h3 = ((const float2*)(g_hseq + (base + 3) * HID))[lane];
        ((float2*)hst[wid][0])[lane] = h0;
        ((float2*)hst[wid][1])[lane] = h1;
        ((float2*)hst[wid][2])[lane] = h2;
        ((float2*)hst[wid][3])[lane] = h3;
        __syncwarp();

        const u64* hA = (const u64*)hst[wid][0];
        const u64* hB = (const u64*)hst[wid][1];
        const u64* hC = (const u64*)hst[wid][2];
        const u64* hD = (const u64*)hst[wid][3];
        u64 aA0 = 0, aA1 = 0, aB0 = 0, aB1 = 0;
        u64 aC0 = 0, aC1 = 0, aD0 = 0, aD1 = 0;
#pragma unroll
        for (int k2 = 0; k2 < 32; ++k2) {
            const u64 w0 = w2p[k2][j0];
            const u64 w1 = w2p[k2][j1];
            const u64 pA = hA[k2];
            const u64 pB = hB[k2];
            const u64 pC = hC[k2];
            const u64 pD = hD[k2];
            aA0 = fma2(w0, pA, aA0);  aA1 = fma2(w1, pA, aA1);
            aB0 = fma2(w0, pB, aB0);  aB1 = fma2(w1, pB, aB1);
            aC0 = fma2(w0, pC, aC0);  aC1 = fma2(w1, pC, aC1);
            aD0 = fma2(w0, pD, aD0);  aD1 = fma2(w1, pD, aD1);
        }

        u64 acc0[4] = {aA0, aB0, aC0, aD0};
        u64 acc1[4] = {aA1, aB1, aC1, aD1};
#pragma unroll
        for (int rr = 0; rr < 4; ++rr) {
            float o0 = psum(acc0[rr]) + bo0;
            float o1 = psum(acc1[rr]) + bo1;
            float s = o0 + o1;
#pragma unroll
            for (int o = 16; o; o >>= 1) s += __shfl_xor_sync(0xffffffffu, s, o);
            const float m = s * (1.f / 64.f);
            const float d0 = o0 - m, d1 = o1 - m;
            float q = d0 * d0 + d1 * d1;
#pragma unroll
            for (int o = 16; o; o >>= 1) q += __shfl_xor_sync(0xffffffffu, q, o);
            const float rs = rsqrtf(q * (1.f / 64.f) + EPS);
            const size_t row = base + rr;
            out[row * DPK + j0] = d0 * rs * lg0 + lb0;
            out[row * DPK + j1] = d1 * rs * lg1 + lb1;
        }
        __syncwarp();   // hst slot reused next iteration
    }
}

// ================== launcher =================================================
extern "C" void kernel_launch(void* const* d_in, const int* in_sizes, int n_in,
                              void* d_out, int out_size)
{
    const float* drug = (const float*)d_in[0];
    const float* w1   = (const float*)d_in[1];
    const float* b1   = (const float*)d_in[2];
    const float* ln1g = (const float*)d_in[3];
    const float* ln1b = (const float*)d_in[4];
    const float* Wih  = (const float*)d_in[5];
    const float* bih  = (const float*)d_in[6];
    const float* Whh  = (const float*)d_in[7];
    const float* bhh  = (const float*)d_in[8];
    const float* w2   = (const float*)d_in[9];
    const float* b2   = (const float*)d_in[10];
    const float* ln2g = (const float*)d_in[11];
    const float* ln2b = (const float*)d_in[12];
    float* out = (float*)d_out;

    k_inproj<<<NROWS / 8, 256>>>(drug, w1, b1, ln1g, ln1b);
    k_gi<<<888, 192>>>(Wih, bih, bhh);
    k_gru<<<BB / CH, 256>>>(Whh, bhh);
    k_outproj<<<2048, 256>>>(w2, b2, ln2g, ln2b, out);
}

// round 11
// speedup vs baseline: 1.0409x; 1.0409x over previous
#include <cuda_runtime.h>
#include <cuda_bf16.h>
#include <cstdint>

// Problem constants
#define BB   256
#define TT   2048
#define IND  6
#define HID  64
#define GG   192          // 3*HID
#define DPK  64
#define NROWS (BB*TT)     // 524288
#define EPS  1e-5f
#define CH   2            // chains per GRU CTA

typedef unsigned long long u64;

// ---------------- scratch (allocation-free: __device__ globals) -------------
__device__ float g_x[(size_t)NROWS * HID];       // 128 MB : post input-proj activations
// gi J-MAJOR: index = row*GG + gate*64 + j  (warp-coalesced loads in k_gru)
// biases pre-folded: r,z gates carry b_ih+b_hh; n gate carries b_ih only.
__device__ float g_gi[(size_t)NROWS * GG];       // 402 MB
__device__ float g_hseq[(size_t)NROWS * HID];    // 128 MB : GRU hidden states [b][t][j]

// ---------------- packed f32x2 helpers --------------------------------------
__device__ __forceinline__ u64 fma2(u64 a, u64 b, u64 c) {
    u64 d;
    asm("fma.rn.f32x2 %0, %1, %2, %3;" : "=l"(d) : "l"(a), "l"(b), "l"(c));
    return d;
}
__device__ __forceinline__ u64 add2(u64 a, u64 b) {
    u64 d;
    asm("add.rn.f32x2 %0, %1, %2;" : "=l"(d) : "l"(a), "l"(b));
    return d;
}
__device__ __forceinline__ u64 pack2(float a, float b) {
    u64 r;
    asm("mov.b64 %0, {%1,%2};" : "=l"(r) : "f"(a), "f"(b));
    return r;
}
__device__ __forceinline__ float psum(u64 a) {
    return __uint_as_float((unsigned)(a & 0xffffffffull)) +
           __uint_as_float((unsigned)(a >> 32));
}

// EXACT-path activations (validated rel_err ~2.5e-7 over the full recurrence).
// tanh.approx is banned inside the recurrence (R5: errors compound to ~0.15).
__device__ __forceinline__ float sigmoidf_(float x) {
    return __fdividef(1.f, 1.f + __expf(-x));
}
__device__ __forceinline__ float tanhf_(float x) {
    float e = __expf(2.f * x);
    return 1.f - __fdividef(2.f, e + 1.f);   // safe at e->inf (->1) and e->0 (->-1)
}

// ================== K1a: input proj + LN + exact GELU ======================
// one warp per (b,t) row; each lane owns output cols lane, lane+32
__global__ void k_inproj(const float* __restrict__ ce,
                         const float* __restrict__ w1,
                         const float* __restrict__ b1,
                         const float* __restrict__ g1,
                         const float* __restrict__ bb1)
{
    const int wid  = threadIdx.x >> 5;
    const int lane = threadIdx.x & 31;
    const size_t row = (size_t)blockIdx.x * 8 + wid;   // grid = NROWS/8

    const float* c = ce + row * IND;
    float v0 = b1[lane], v1 = b1[lane + 32];
#pragma unroll
    for (int i = 0; i < IND; ++i) {
        float ci = __ldg(c + i);
        v0 = fmaf(ci, w1[i * HID + lane],      v0);
        v1 = fmaf(ci, w1[i * HID + lane + 32], v1);
    }
    float s = v0 + v1;
#pragma unroll
    for (int o = 16; o; o >>= 1) s += __shfl_xor_sync(0xffffffffu, s, o);
    const float m = s * (1.f / 64.f);
    const float d0 = v0 - m, d1 = v1 - m;
    float q = d0 * d0 + d1 * d1;
#pragma unroll
    for (int o = 16; o; o >>= 1) q += __shfl_xor_sync(0xffffffffu, q, o);
    const float rs = rsqrtf(q * (1.f / 64.f) + EPS);
    const float y0 = d0 * rs * g1[lane]      + bb1[lane];
    const float y1 = d1 * rs * g1[lane + 32] + bb1[lane + 32];
    const float k = 0.70710678118654752f;
    g_x[row * HID + lane]      = 0.5f * y0 * (1.f + erff(y0 * k));
    g_x[row * HID + lane + 32] = 0.5f * y1 * (1.f + erff(y1 * k));
}

// ================== K1b: gi = x @ W_ih^T + bias  (j-major output) ==========
// gate-stationary: thread g keeps W_ih[g,:] in 32 packed-u64 registers,
// 8 rows of x staged in smem per iteration; direct coalesced output write.
// Bias folding: gates r,z get b_ih+b_hh; gate n gets b_ih only.
__global__ void __launch_bounds__(192) k_gi(const float* __restrict__ Wih,
                                            const float* __restrict__ bih,
                                            const float* __restrict__ bhh)
{
    const int g = threadIdx.x;
    u64 w[32];
    const u64* wrow = (const u64*)(Wih + g * HID);
#pragma unroll
    for (int k = 0; k < 32; ++k) w[k] = wrow[k];
    const int gate = g >> 6;
    const float bi = bih[g] + (gate < 2 ? bhh[g] : 0.f);

    __shared__ __align__(16) float x_sh[8 * HID];

    for (size_t r0 = (size_t)blockIdx.x * 8; r0 < (size_t)NROWS;
         r0 += (size_t)gridDim.x * 8) {
        if (g < 128)
            ((float4*)x_sh)[g] = ((const float4*)(g_x + r0 * HID))[g];
        __syncthreads();
#pragma unroll
        for (int rr = 0; rr < 8; ++rr) {
            u64 a0 = 0, a1 = 0;
            const ulonglong2* xv = (const ulonglong2*)(x_sh + rr * HID);
#pragma unroll
            for (int kk = 0; kk < 16; ++kk) {
                ulonglong2 p = xv[kk];
                a0 = fma2(w[2 * kk],     p.x, a0);
                a1 = fma2(w[2 * kk + 1], p.y, a1);
            }
            g_gi[(r0 + rr) * GG + g] = psum(a0) + psum(a1) + bi;
        }
        __syncthreads();
    }
}

// ================== K2: sequential GRU recurrence (GATE-SPLIT) ==============
// grid = 128 CTAs, block = 384 threads = 2 chains x 192 threads (6 warps).
// Thread (chain, gate, j) owns ONE W_hh row (32 u64 = 64 regs, ~85 total:
// zero spill pressure). 1536 warps chip-wide -> ~3 warps/SMSP: per-warp
// issue is only ~96 fma2-cycles/step, so co-resident warps fill each
// other's latency windows (the 2-warp-chain designs R8/R10 could not get
// both full-grid AND co-residency; 6-warp chains can).
// Per step: all threads dot(W_row, h) from smem ring; r,z threads write
// sigmoid to handoff smem; bar; n threads read r,z, do tanh + h update,
// write h to ring; bar. Two 192-thread named barriers per step.
// gi j-major -> thread g loads gib[t*GG] : 192 consecutive floats per chain,
// perfectly coalesced; in-place reload at prefetch distance 4.
// h ring: 16 slots; coalesced float4 flush of 8 steps every 8 steps.
__global__ void __launch_bounds__(384, 1) k_gru(const float* __restrict__ Whh,
                                                const float* __restrict__ bhh)
{
    const int tid   = threadIdx.x;
    const int chain = tid / 192;         // 0..1
    const int g     = tid % 192;
    const int gate  = g >> 6;            // 0=r, 1=z, 2=n
    const int j     = g & 63;
    const size_t brow = (size_t)blockIdx.x * CH + chain;
    const unsigned barid = 1 + chain;

    __shared__ __align__(16) float ring[16][CH][64];  // 8 KB h history
    __shared__ float rsm[CH][64];
    __shared__ float zsm[CH][64];

    // this thread's gate row, register-resident: 32 u64
    u64 w[32];
    {
        const u64* wrow = (const u64*)(Whh + (size_t)g * HID);
#pragma unroll
        for (int k = 0; k < 32; ++k) w[k] = wrow[k];
    }
    const float bhn = (gate == 2) ? bhh[128 + j] : 0.f;

    if (g < 64) ring[15][chain][j] = 0.f;   // h_{-1} = 0
    float hprev = 0.f;                       // live only on n-threads

    const float* gib = g_gi + brow * (size_t)TT * GG + g;
    float* hbase = g_hseq + brow * (size_t)TT * HID;

    // gi buffer: this thread's own gate value for the next 4 steps,
    // reloaded in place right after consumption (coalesced LDG.32).
    float c0 = __ldg(gib + 0 * GG);
    float c1 = __ldg(gib + 1 * GG);
    float c2 = __ldg(gib + 2 * GG);
    float c3 = __ldg(gib + 3 * GG);

    asm volatile("bar.sync %0, 192;" :: "r"(barid) : "memory");

    auto step = [&](const int t, const float gi_cur) {
        const ulonglong2* hv = (const ulonglong2*)ring[(t + 15) & 15][chain];
        u64 a0 = 0, a1 = 0;
#pragma unroll
        for (int kk = 0; kk < 16; ++kk) {      // full 64-wide dot: 16 x LDS.128
            const ulonglong2 p = hv[kk];
            a0 = fma2(w[2 * kk],     p.x, a0);
            a1 = fma2(w[2 * kk + 1], p.y, a1);
        }
        const float pd = psum(add2(a0, a1));

        if (gate == 0)      rsm[chain][j] = sigmoidf_(gi_cur + pd);
        else if (gate == 1) zsm[chain][j] = sigmoidf_(gi_cur + pd);
        asm volatile("bar.sync %0, 192;" :: "r"(barid) : "memory");

        if (gate == 2) {
            const float r = rsm[chain][j];
            const float z = zsm[chain][j];
            const float n = tanhf_(gi_cur + r * (pd + bhn));
            const float hnew = fmaf(z, hprev - n, n);   // (1-z)*n + z*h
            ring[t & 15][chain][j] = hnew;
            hprev = hnew;
        }
        asm volatile("bar.sync %0, 192;" :: "r"(barid) : "memory");
    };

#pragma unroll 1
    for (int blk = 0; blk < TT / 4; ++blk) {
        const int t0 = blk * 4;
        const bool pf = (blk + 1 < TT / 4);
        const float* p = gib + (size_t)(t0 + 4) * GG;

        { const float gc = c0; if (pf) c0 = __ldg(p + 0 * GG); step(t0 + 0, gc); }
        { const float gc = c1; if (pf) c1 = __ldg(p + 1 * GG); step(t0 + 1, gc); }
        { const float gc = c2; if (pf) c2 = __ldg(p + 2 * GG); step(t0 + 2, gc); }
        { const float gc = c3; if (pf) c3 = __ldg(p + 3 * GG); step(t0 + 3, gc); }

        if (blk & 1) {
            // flush steps tb..tb+7 (ring slots (tb&15)..+7), coalesced:
            // 128 of the chain's 192 threads each move one float4.
            // Safe: these slots are next overwritten >= 9 barriers later.
            const int tb = t0 - 4;               // multiple of 8
            const int sb = tb & 15;              // 0 or 8
            if (g < 128) {
                const int toff = g >> 4;         // 0..7
                const int jq   = g & 15;         // float4 index within row
                const float4 v = ((const float4*)ring[sb + toff][chain])[jq];
                ((float4*)(hbase + (size_t)(tb + toff) * HID))[jq] = v;
            }
        }
    }
}

// ================== K3: out proj + LN =======================================
// 256 threads / 8 warps; w2 packed in smem [k2][64] (conflict-free LDS.64);
// each warp processes 4 rows per iteration (MLP_p1=4), lane owns cols lane,lane+32.
__global__ void __launch_bounds__(256) k_outproj(const float* __restrict__ w2,
                                                 const float* __restrict__ b2,
                                                 const float* __restrict__ g2,
                                                 const float* __restrict__ bb2,
                                                 float* __restrict__ out)
{
    const int tid  = threadIdx.x;
    const int wid  = tid >> 5;
    const int lane = tid & 31;
    const int j0 = lane, j1 = lane + 32;

    __shared__ __align__(16) u64   w2p[32][64];     // 16 KB
    __shared__ __align__(16) float hst[8][4][64];   // 8 KB, per-warp staging

    for (int idx = tid; idx < 32 * 64; idx += 256) {
        const int k2 = idx >> 6, jj = idx & 63;
        w2p[k2][jj] = pack2(w2[(size_t)(2 * k2) * DPK + jj],
                            w2[(size_t)(2 * k2 + 1) * DPK + jj]);
    }
    __syncthreads();

    const float bo0 = b2[j0], bo1 = b2[j1];
    const float lg0 = g2[j0], lg1 = g2[j1];
    const float lb0 = bb2[j0], lb1 = bb2[j1];

    const size_t stride = (size_t)gridDim.x * 32;
    for (size_t base = (size_t)blockIdx.x * 32 + wid * 4; base < (size_t)NROWS;
         base += stride) {
        // 4 rows in flight (front-batched LDG.64s)
        const float2 h0 = ((const float2*)(g_hseq + (base + 0) * HID))[lane];
        const float2 h1 = ((const float2*)(g_hseq + (base + 1) * HID))[lane];
        const float2 h2 = ((const float2*)(g_hseq + (base + 2) * HID))[lane];
        const float2 h3 = ((const float2*)(g_hseq + (base + 3) * HID))[lane];
        ((float2*)hst[wid][0])[lane] = h0;
        ((float2*)hst[wid][1])[lane] = h1;
        ((float2*)hst[wid][2])[lane] = h2;
        ((float2*)hst[wid][3])[lane] = h3;
        __syncwarp();

        const u64* hA = (const u64*)hst[wid][0];
        const u64* hB = (const u64*)hst[wid][1];
        const u64* hC = (const u64*)hst[wid][2];
        const u64* hD = (const u64*)hst[wid][3];
        u64 aA0 = 0, aA1 = 0, aB0 = 0, aB1 = 0;
        u64 aC0 = 0, aC1 = 0, aD0 = 0, aD1 = 0;
#pragma unroll
        for (int k2 = 0; k2 < 32; ++k2) {
            const u64 w0 = w2p[k2][j0];
            const u64 w1 = w2p[k2][j1];
            const u64 pA = hA[k2];
            const u64 pB = hB[k2];
            const u64 pC = hC[k2];
            const u64 pD = hD[k2];
            aA0 = fma2(w0, pA, aA0);  aA1 = fma2(w1, pA, aA1);
            aB0 = fma2(w0, pB, aB0);  aB1 = fma2(w1, pB, aB1);
            aC0 = fma2(w0, pC, aC0);  aC1 = fma2(w1, pC, aC1);
            aD0 = fma2(w0, pD, aD0);  aD1 = fma2(w1, pD, aD1);
        }

        u64 acc0[4] = {aA0, aB0, aC0, aD0};
        u64 acc1[4] = {aA1, aB1, aC1, aD1};
#pragma unroll
        for (int rr = 0; rr < 4; ++rr) {
            float o0 = psum(acc0[rr]) + bo0;
            float o1 = psum(acc1[rr]) + bo1;
            float s = o0 + o1;
#pragma unroll
            for (int o = 16; o; o >>= 1) s += __shfl_xor_sync(0xffffffffu, s, o);
            const float m = s * (1.f / 64.f);
            const float d0 = o0 - m, d1 = o1 - m;
            float q = d0 * d0 + d1 * d1;
#pragma unroll
            for (int o = 16; o; o >>= 1) q += __shfl_xor_sync(0xffffffffu, q, o);
            const float rs = rsqrtf(q * (1.f / 64.f) + EPS);
            const size_t row = base + rr;
            out[row * DPK + j0] = d0 * rs * lg0 + lb0;
            out[row * DPK + j1] = d1 * rs * lg1 + lb1;
        }
        __syncwarp();   // hst slot reused next iteration
    }
}

// ================== launcher =================================================
extern "C" void kernel_launch(void* const* d_in, const int* in_sizes, int n_in,
                              void* d_out, int out_size)
{
    const float* drug = (const float*)d_in[0];
    const float* w1   = (const float*)d_in[1];
    const float* b1   = (const float*)d_in[2];
    const float* ln1g = (const float*)d_in[3];
    const float* ln1b = (const float*)d_in[4];
    const float* Wih  = (const float*)d_in[5];
    const float* bih  = (const float*)d_in[6];
    const float* Whh  = (const float*)d_in[7];
    const float* bhh  = (const float*)d_in[8];
    const float* w2   = (const float*)d_in[9];
    const float* b2   = (const float*)d_in[10];
    const float* ln2g = (const float*)d_in[11];
    const float* ln2b = (const float*)d_in[12];
    float* out = (float*)d_out;

    k_inproj<<<NROWS / 8, 256>>>(drug, w1, b1, ln1g, ln1b);
    k_gi<<<888, 192>>>(Wih, bih, bhh);
    k_gru<<<BB / CH, 384>>>(Whh, bhh);
    k_outproj<<<2048, 256>>>(w2, b2, ln2g, ln2b, out);
}

// round 12
// speedup vs baseline: 1.5543x; 1.4933x over previous
#include <cuda_runtime.h>
#include <cuda_bf16.h>
#include <cstdint>

// Problem constants
#define BB   256
#define TT   2048
#define IND  6
#define HID  64
#define GG   192          // 3*HID
#define DPK  64
#define NROWS (BB*TT)     // 524288
#define EPS  1e-5f
#define CH   2            // chains per GRU CTA
#define NBLK (TT/8)       // 256 gi blocks of 8 timesteps

typedef unsigned long long u64;

// ---------------- scratch (allocation-free: __device__ globals) -------------
__device__ float g_x[(size_t)NROWS * HID];       // 128 MB : post input-proj activations
// gi J-MAJOR: index = row*GG + gate*64 + j; produced INSIDE k_gru by gi warps.
// biases pre-folded: r,z gates carry b_ih+b_hh; n gate carries b_ih only.
__device__ float g_gi[(size_t)NROWS * GG];       // 402 MB
__device__ float g_hseq[(size_t)NROWS * HID];    // 128 MB : GRU hidden states [b][t][j]

// ---------------- packed f32x2 helpers --------------------------------------
__device__ __forceinline__ u64 fma2(u64 a, u64 b, u64 c) {
    u64 d;
    asm("fma.rn.f32x2 %0, %1, %2, %3;" : "=l"(d) : "l"(a), "l"(b), "l"(c));
    return d;
}
__device__ __forceinline__ u64 add2(u64 a, u64 b) {
    u64 d;
    asm("add.rn.f32x2 %0, %1, %2;" : "=l"(d) : "l"(a), "l"(b));
    return d;
}
__device__ __forceinline__ u64 pack2(float a, float b) {
    u64 r;
    asm("mov.b64 %0, {%1,%2};" : "=l"(r) : "f"(a), "f"(b));
    return r;
}
__device__ __forceinline__ float psum(u64 a) {
    return __uint_as_float((unsigned)(a & 0xffffffffull)) +
           __uint_as_float((unsigned)(a >> 32));
}
// plain (coherent) global load — rec must NOT use __ldg for gi: the RO/NC path
// may serve stale data for values written during this kernel by gi warps.
__device__ __forceinline__ float ldg_plain(const float* p) {
    float v;
    asm volatile("ld.global.f32 %0, [%1];" : "=f"(v) : "l"(p));
    return v;
}
__device__ __forceinline__ unsigned ld_acquire_u32(const unsigned* p) {
    unsigned v;
    asm volatile("ld.acquire.cta.u32 %0, [%1];" : "=r"(v) : "l"(p) : "memory");
    return v;
}
__device__ __forceinline__ void st_release_u32(unsigned* p, unsigned v) {
    asm volatile("st.release.cta.u32 [%0], %1;" :: "l"(p), "r"(v) : "memory");
}

// EXACT-path activations (validated rel_err ~2.5e-7 over the full recurrence).
// tanh.approx is banned inside the recurrence (R5: errors compound to ~0.15).
__device__ __forceinline__ float sigmoidf_(float x) {
    return __fdividef(1.f, 1.f + __expf(-x));
}
__device__ __forceinline__ float tanhf_(float x) {
    float e = __expf(2.f * x);
    return 1.f - __fdividef(2.f, e + 1.f);   // safe at e->inf (->1) and e->0 (->-1)
}

// ================== K1a: input proj + LN + exact GELU ======================
// one warp per (b,t) row; each lane owns output cols lane, lane+32
__global__ void k_inproj(const float* __restrict__ ce,
                         const float* __restrict__ w1,
                         const float* __restrict__ b1,
                         const float* __restrict__ g1,
                         const float* __restrict__ bb1)
{
    const int wid  = threadIdx.x >> 5;
    const int lane = threadIdx.x & 31;
    const size_t row = (size_t)blockIdx.x * 8 + wid;   // grid = NROWS/8

    const float* c = ce + row * IND;
    float v0 = b1[lane], v1 = b1[lane + 32];
#pragma unroll
    for (int i = 0; i < IND; ++i) {
        float ci = __ldg(c + i);
        v0 = fmaf(ci, w1[i * HID + lane],      v0);
        v1 = fmaf(ci, w1[i * HID + lane + 32], v1);
    }
    float s = v0 + v1;
#pragma unroll
    for (int o = 16; o; o >>= 1) s += __shfl_xor_sync(0xffffffffu, s, o);
    const float m = s * (1.f / 64.f);
    const float d0 = v0 - m, d1 = v1 - m;
    float q = d0 * d0 + d1 * d1;
#pragma unroll
    for (int o = 16; o; o >>= 1) q += __shfl_xor_sync(0xffffffffu, q, o);
    const float rs = rsqrtf(q * (1.f / 64.f) + EPS);
    const float y0 = d0 * rs * g1[lane]      + bb1[lane];
    const float y1 = d1 * rs * g1[lane + 32] + bb1[lane + 32];
    const float k = 0.70710678118654752f;
    g_x[row * HID + lane]      = 0.5f * y0 * (1.f + erff(y0 * k));
    g_x[row * HID + lane + 32] = 0.5f * y1 * (1.f + erff(y1 * k));
}

// ================== K2: FUSED gi-producer + GRU recurrence ===================
// grid = 128 CTAs, block = 256 threads, 2 chains:
//   tid   0- 63 : gi producer, chain 0  (warps 0,1 -- LOW wid = low priority)
//   tid  64-127 : gi producer, chain 1  (warps 2,3)
//   tid 128-191 : recurrence,  chain 0  (warps 4,5 -- HIGH wid = priority)
//   tid 192-255 : recurrence,  chain 1  (warps 6,7)
// SMSP s hosts warp s (gi) + warp s+4 (rec): the gi warp has NO per-step
// barrier, so it streams fma2 into the rec warp's exposed-latency windows
// (R8-R11 established that barrier-synchronized co-residents stall in
// lockstep; only barrier-free work fills the ~390cyc/step serial window).
//
// gi warps: thread j owns W_ih rows {j, 64+j, 128+j} (96 u64 regs); per
// 8-step block: stage x rows in smem (2 private 64-thread bars), compute
// 24 dots, STG to g_gi (coalesced), publish progress via st.release flag.
// rec warps: EXACT R8 inner loop (full 64-wide dots from 16-slot smem h
// ring, 96 u64 weight regs, coalesced float4 h flush every 8 steps), with
// gi loads switched to coherent ld.global and an ld.acquire flag gate
// every 8 steps (passes first-try after gi's ~3-block head start).
__global__ void __launch_bounds__(256, 1) k_gru(const float* __restrict__ Wih,
                                                const float* __restrict__ bih,
                                                const float* __restrict__ Whh,
                                                const float* __restrict__ bhh)
{
    const int tid   = threadIdx.x;
    const int role  = tid >> 7;            // 0 = gi producer, 1 = recurrence
    const int chain = (tid >> 6) & 1;
    const int j     = tid & 63;
    const size_t brow = (size_t)blockIdx.x * CH + chain;

    __shared__ __align__(16) float ring[16][CH][64];  // 8 KB h history
    __shared__ __align__(16) float xsh[CH][8][64];    // 4 KB x staging (gi)
    __shared__ unsigned flags[CH];                    // gi blocks completed

    if (tid < CH) flags[tid] = 0;
    __syncthreads();                                  // flags visible to all

    if (role == 0) {
        // ================= gi producer =================
        const unsigned gibar = 3 + chain;             // 64-thread named barrier
        u64 wr[32], wz[32], wn[32];
        {
            const u64* rrow = (const u64*)(Wih + (size_t)j * HID);
            const u64* zrow = (const u64*)(Wih + (size_t)(64 + j) * HID);
            const u64* nrow = (const u64*)(Wih + (size_t)(128 + j) * HID);
#pragma unroll
            for (int k = 0; k < 32; ++k) { wr[k] = rrow[k]; wz[k] = zrow[k]; wn[k] = nrow[k]; }
        }
        const float bir = bih[j]       + bhh[j];
        const float biz = bih[64 + j]  + bhh[64 + j];
        const float bin = bih[128 + j];

        const float* xb   = g_x  + brow * (size_t)TT * HID;
        float*       gout = g_gi + brow * (size_t)TT * GG;

        float xr[8];
#pragma unroll
        for (int r = 0; r < 8; ++r) xr[r] = __ldg(xb + (size_t)r * HID + j);

#pragma unroll 1
        for (int b = 0; b < NBLK; ++b) {
            asm volatile("bar.sync %0, 64;" :: "r"(gibar) : "memory");
            if (j == 0 && b) st_release_u32(&flags[chain], (unsigned)b);
#pragma unroll
            for (int r = 0; r < 8; ++r) xsh[chain][r][j] = xr[r];
            asm volatile("bar.sync %0, 64;" :: "r"(gibar) : "memory");
            if (b + 1 < NBLK) {
                const float* xn = xb + (size_t)(b + 1) * 8 * HID + j;
#pragma unroll
                for (int r = 0; r < 8; ++r) xr[r] = __ldg(xn + (size_t)r * HID);
            }
#pragma unroll
            for (int r = 0; r < 8; ++r) {
                const ulonglong2* xv = (const ulonglong2*)xsh[chain][r];
                u64 ar0 = 0, ar1 = 0, az0 = 0, az1 = 0, an0 = 0, an1 = 0;
#pragma unroll
                for (int kk = 0; kk < 16; ++kk) {
                    const ulonglong2 p = xv[kk];        // LDS.128 broadcast
                    ar0 = fma2(wr[2 * kk],     p.x, ar0);
                    az0 = fma2(wz[2 * kk],     p.x, az0);
                    an0 = fma2(wn[2 * kk],     p.x, an0);
                    ar1 = fma2(wr[2 * kk + 1], p.y, ar1);
                    az1 = fma2(wz[2 * kk + 1], p.y, az1);
                    an1 = fma2(wn[2 * kk + 1], p.y, an1);
                }
                float* d = gout + (size_t)(b * 8 + r) * GG + j;
                d[0]   = psum(add2(ar0, ar1)) + bir;
                d[64]  = psum(add2(az0, az1)) + biz;
                d[128] = psum(add2(an0, an1)) + bin;
            }
        }
        asm volatile("bar.sync %0, 64;" :: "r"(gibar) : "memory");
        if (j == 0) st_release_u32(&flags[chain], (unsigned)NBLK);

    } else {
        // ================= recurrence (R8 inner loop) =================
        const unsigned barid = 1 + chain;             // 64-thread named barrier
        u64 wr[32], wz[32], wn[32];
        {
            const u64* rrow = (const u64*)(Whh + (size_t)j * HID);
            const u64* zrow = (const u64*)(Whh + (size_t)(64 + j) * HID);
            const u64* nrow = (const u64*)(Whh + (size_t)(128 + j) * HID);
#pragma unroll
            for (int k = 0; k < 32; ++k) { wr[k] = rrow[k]; wz[k] = zrow[k]; wn[k] = nrow[k]; }
        }
        const float bhn = bhh[128 + j];

        ring[15][chain][j] = 0.f;                     // h_{-1} = 0
        float hprev = 0.f;

        const float* gib = g_gi + brow * (size_t)TT * GG + j;
        float* hbase = g_hseq + brow * (size_t)TT * HID;

        // wait for gi blocks 0,1 then prime the 4-step gi buffer
        while (ld_acquire_u32(&flags[chain]) < 2u) __nanosleep(128);
        float cr0 = ldg_plain(gib + 0 * GG), cz0 = ldg_plain(gib + 0 * GG + 64), cn0 = ldg_plain(gib + 0 * GG + 128);
        float cr1 = ldg_plain(gib + 1 * GG), cz1 = ldg_plain(gib + 1 * GG + 64), cn1 = ldg_plain(gib + 1 * GG + 128);
        float cr2 = ldg_plain(gib + 2 * GG), cz2 = ldg_plain(gib + 2 * GG + 64), cn2 = ldg_plain(gib + 2 * GG + 128);
        float cr3 = ldg_plain(gib + 3 * GG), cz3 = ldg_plain(gib + 3 * GG + 64), cn3 = ldg_plain(gib + 3 * GG + 128);

        asm volatile("bar.sync %0, 64;" :: "r"(barid) : "memory");

        auto step = [&](const int t, const float ir, const float iz, const float inn) {
            const ulonglong2* hv = (const ulonglong2*)ring[(t + 15) & 15][chain];
            u64 ar = 0, az = 0, an = 0;
#pragma unroll
            for (int kk = 0; kk < 16; ++kk) {          // full 64-wide dot
                const ulonglong2 p = hv[kk];           // LDS.128 broadcast
                ar = fma2(wr[2 * kk],     p.x, ar);
                az = fma2(wz[2 * kk],     p.x, az);
                an = fma2(wn[2 * kk],     p.x, an);
                ar = fma2(wr[2 * kk + 1], p.y, ar);
                az = fma2(wz[2 * kk + 1], p.y, az);
                an = fma2(wn[2 * kk + 1], p.y, an);
            }
            const float r = sigmoidf_(ir + psum(ar));  // biases pre-folded in gi
            const float z = sigmoidf_(iz + psum(az));
            const float n = tanhf_(inn + r * (psum(an) + bhn));
            const float hnew = fmaf(z, hprev - n, n);  // (1-z)*n + z*h
            ring[t & 15][chain][j] = hnew;
            hprev = hnew;
            asm volatile("bar.sync %0, 64;" :: "r"(barid) : "memory");
        };

#pragma unroll 1
        for (int blk = 0; blk < TT / 4; ++blk) {
            const int t0 = blk * 4;
            if ((blk & 1) == 0 && blk) {
                // entering t0=8m: prefetch will reach gi step 8m+11 (block m+1)
                const unsigned need = (unsigned)min((blk >> 1) + 2, NBLK);
                if (ld_acquire_u32(&flags[chain]) < need)
                    while (ld_acquire_u32(&flags[chain]) < need) __nanosleep(128);
            }
            const bool pf = (blk + 1 < TT / 4);
            const float* p = gib + (size_t)(t0 + 4) * GG;

            { const float ir = cr0, iz = cz0, inn = cn0;
              if (pf) { cr0 = ldg_plain(p + 0 * GG); cz0 = ldg_plain(p + 0 * GG + 64); cn0 = ldg_plain(p + 0 * GG + 128); }
              step(t0 + 0, ir, iz, inn); }
            { const float ir = cr1, iz = cz1, inn = cn1;
              if (pf) { cr1 = ldg_plain(p + 1 * GG); cz1 = ldg_plain(p + 1 * GG + 64); cn1 = ldg_plain(p + 1 * GG + 128); }
              step(t0 + 1, ir, iz, inn); }
            { const float ir = cr2, iz = cz2, inn = cn2;
              if (pf) { cr2 = ldg_plain(p + 2 * GG); cz2 = ldg_plain(p + 2 * GG + 64); cn2 = ldg_plain(p + 2 * GG + 128); }
              step(t0 + 2, ir, iz, inn); }
            { const float ir = cr3, iz = cz3, inn = cn3;
              if (pf) { cr3 = ldg_plain(p + 3 * GG); cz3 = ldg_plain(p + 3 * GG + 64); cn3 = ldg_plain(p + 3 * GG + 128); }
              step(t0 + 3, ir, iz, inn); }

            if (blk & 1) {
                // flush steps tb..tb+7 (ring slots (tb&15)..+7), coalesced.
                // Safe: these slots are next overwritten >= 9 barriers later.
                const int tb = t0 - 4;               // multiple of 8
                const int sb = tb & 15;              // 0 or 8
#pragma unroll
                for (int q = 0; q < 2; ++q) {
                    const int idx  = q * 64 + j;     // 0..127
                    const int toff = idx >> 4;       // 0..7
                    const int jq   = idx & 15;       // float4 index within row
                    const float4 v = ((const float4*)ring[sb + toff][chain])[jq];
                    ((float4*)(hbase + (size_t)(tb + toff) * HID))[jq] = v;
                }
            }
        }
    }
}

// ================== K3: out proj + LN =======================================
// 256 threads / 8 warps; w2 packed in smem [k2][64] (conflict-free LDS.64);
// each warp processes 4 rows per iteration (MLP_p1=4), lane owns cols lane,lane+32.
__global__ void __launch_bounds__(256) k_outproj(const float* __restrict__ w2,
                                                 const float* __restrict__ b2,
                                                 const float* __restrict__ g2,
                                                 const float* __restrict__ bb2,
                                                 float* __restrict__ out)
{
    const int tid  = threadIdx.x;
    const int wid  = tid >> 5;
    const int lane = tid & 31;
    const int j0 = lane, j1 = lane + 32;

    __shared__ __align__(16) u64   w2p[32][64];     // 16 KB
    __shared__ __align__(16) float hst[8][4][64];   // 8 KB, per-warp staging

    for (int idx = tid; idx < 32 * 64; idx += 256) {
        const int k2 = idx >> 6, jj = idx & 63;
        w2p[k2][jj] = pack2(w2[(size_t)(2 * k2) * DPK + jj],
                            w2[(size_t)(2 * k2 + 1) * DPK + jj]);
    }
    __syncthreads();

    const float bo0 = b2[j0], bo1 = b2[j1];
    const float lg0 = g2[j0], lg1 = g2[j1];
    const float lb0 = bb2[j0], lb1 = bb2[j1];

    const size_t stride = (size_t)gridDim.x * 32;
    for (size_t base = (size_t)blockIdx.x * 32 + wid * 4; base < (size_t)NROWS;
         base += stride) {
        // 4 rows in flight (front-batched LDG.64s)
        const float2 h0 = ((const float2*)(g_hseq + (base + 0) * HID))[lane];
        const float2 h1 = ((const float2*)(g_hseq + (base + 1) * HID))[lane];
        const float2 h2 = ((const float2*)(g_hseq + (base + 2) * HID))[lane];
        const float2 h3 = ((const float2*)(g_hseq + (base + 3) * HID))[lane];
        ((float2*)hst[wid][0])[lane] = h0;
        ((float2*)hst[wid][1])[lane] = h1;
        ((float2*)hst[wid][2])[lane] = h2;
        ((float2*)hst[wid][3])[lane] = h3;
        __syncwarp();

        const u64* hA = (const u64*)hst[wid][0];
        const u64* hB = (const u64*)hst[wid][1];
        const u64* hC = (const u64*)hst[wid][2];
        const u64* hD = (const u64*)hst[wid][3];
        u64 aA0 = 0, aA1 = 0, aB0 = 0, aB1 = 0;
        u64 aC0 = 0, aC1 = 0, aD0 = 0, aD1 = 0;
#pragma unroll
        for (int k2 = 0; k2 < 32; ++k2) {
            const u64 w0 = w2p[k2][j0];
            const u64 w1 = w2p[k2][j1];
            const u64 pA = hA[k2];
            const u64 pB = hB[k2];
            const u64 pC = hC[k2];
            const u64 pD = hD[k2];
            aA0 = fma2(w0, pA, aA0);  aA1 = fma2(w1, pA, aA1);
            aB0 = fma2(w0, pB, aB0);  aB1 = fma2(w1, pB, aB1);
            aC0 = fma2(w0, pC, aC0);  aC1 = fma2(w1, pC, aC1);
            aD0 = fma2(w0, pD, aD0);  aD1 = fma2(w1, pD, aD1);
        }

        u64 acc0[4] = {aA0, aB0, aC0, aD0};
        u64 acc1[4] = {aA1, aB1, aC1, aD1};
#pragma unroll
        for (int rr = 0; rr < 4; ++rr) {
            float o0 = psum(acc0[rr]) + bo0;
            float o1 = psum(acc1[rr]) + bo1;
            float s = o0 + o1;
#pragma unroll
            for (int o = 16; o; o >>= 1) s += __shfl_xor_sync(0xffffffffu, s, o);
            const float m = s * (1.f / 64.f);
            const float d0 = o0 - m, d1 = o1 - m;
            float q = d0 * d0 + d1 * d1;
#pragma unroll
            for (int o = 16; o; o >>= 1) q += __shfl_xor_sync(0xffffffffu, q, o);
            const float rs = rsqrtf(q * (1.f / 64.f) + EPS);
            const size_t row = base + rr;
            out[row * DPK + j0] = d0 * rs * lg0 + lb0;
            out[row * DPK + j1] = d1 * rs * lg1 + lb1;
        }
        __syncwarp();   // hst slot reused next iteration
    }
}

// ================== launcher =================================================
extern "C" void kernel_launch(void* const* d_in, const int* in_sizes, int n_in,
                              void* d_out, int out_size)
{
    const float* drug = (const float*)d_in[0];
    const float* w1   = (const float*)d_in[1];
    const float* b1   = (const float*)d_in[2];
    const float* ln1g = (const float*)d_in[3];
    const float* ln1b = (const float*)d_in[4];
    const float* Wih  = (const float*)d_in[5];
    const float* bih  = (const float*)d_in[6];
    const float* Whh  = (const float*)d_in[7];
    const float* bhh  = (const float*)d_in[8];
    const float* w2   = (const float*)d_in[9];
    const float* b2   = (const float*)d_in[10];
    const float* ln2g = (const float*)d_in[11];
    const float* ln2b = (const float*)d_in[12];
    float* out = (float*)d_out;

    k_inproj<<<NROWS / 8, 256>>>(drug, w1, b1, ln1g, ln1b);
    k_gru<<<BB / CH, 256>>>(Wih, bih, Whh, bhh);
    k_outproj<<<2048, 256>>>(w2, b2, ln2g, ln2b, out);
}